// round 4
// baseline (speedup 1.0000x reference)
#include <cuda_runtime.h>
#include <cstdint>

// Problem constants
#define Bn  16
#define Nn  1024
#define En  3
#define Cc  32
#define ECn 96   // E*C

// Scratch (device-global; no allocation allowed)
__device__ __align__(16) float g_T[Bn * Nn * ECn];     // to_agg = x @ W        [row][ec]
__device__ __align__(16) float g_S[Bn * Nn * ECn];     // self  = x @ W0 + b0   [row][ec]
__device__ __align__(16) float g_sagg[Bn * Nn * ECn];  // dis[m,e] * to_agg     [row][ec]
__device__ __align__(16) float g_dis[Bn * Nn * En];    // deg^-1/2              [row][e]

// ---------------------------------------------------------------------------
// Kernel 1: per-row linear transforms. T = x@W, S = x@W0 + b0.
// Block = 384 threads handles 32 rows; thread (r, g) computes 16 of the 192
// concatenated outputs for row r. W|W0 staged in smem.
// ---------------------------------------------------------------------------
__global__ __launch_bounds__(384) void prep_kernel(
    const float* __restrict__ x,
    const float* __restrict__ W,
    const float* __restrict__ W0,
    const float* __restrict__ b0)
{
    __shared__ __align__(16) float Wc[32 * 192];
    __shared__ float b0s[96];
    __shared__ float xs[32][33];

    int t = threadIdx.x;
    for (int i = t; i < 32 * 192; i += 384) {
        int k = i / 192, j = i % 192;
        Wc[i] = (j < 96) ? W[k * 96 + j] : W0[k * 96 + (j - 96)];
    }
    if (t < 96) b0s[t] = b0[t];

    int row0 = blockIdx.x * 32;
    for (int i = t; i < 32 * 32; i += 384) {
        xs[i >> 5][i & 31] = x[(size_t)(row0 + (i >> 5)) * 32 + (i & 31)];
    }
    __syncthreads();

    int r = t / 12, g = t % 12;  // r in [0,32), g in [0,12): 12*16 = 192 outputs
    int row = row0 + r;

    float acc[16];
#pragma unroll
    for (int j = 0; j < 16; j++) acc[j] = 0.f;

#pragma unroll 4
    for (int k = 0; k < 32; k++) {
        float xv = xs[r][k];
        const float4* wp = (const float4*)&Wc[k * 192 + g * 16];
        float4 w0v = wp[0], w1v = wp[1], w2v = wp[2], w3v = wp[3];
        acc[0]  += xv * w0v.x; acc[1]  += xv * w0v.y; acc[2]  += xv * w0v.z; acc[3]  += xv * w0v.w;
        acc[4]  += xv * w1v.x; acc[5]  += xv * w1v.y; acc[6]  += xv * w1v.z; acc[7]  += xv * w1v.w;
        acc[8]  += xv * w2v.x; acc[9]  += xv * w2v.y; acc[10] += xv * w2v.z; acc[11] += xv * w2v.w;
        acc[12] += xv * w3v.x; acc[13] += xv * w3v.y; acc[14] += xv * w3v.z; acc[15] += xv * w3v.w;
    }

#pragma unroll
    for (int j = 0; j < 16; j++) {
        int ec = g * 16 + j;
        if (ec < 96) g_T[(size_t)row * 96 + ec] = acc[j];
        else         g_S[(size_t)row * 96 + (ec - 96)] = acc[j] + b0s[ec - 96];
    }
}

// ---------------------------------------------------------------------------
// Kernel 2: degrees. One block per (b,n) row: sum 1024*3 floats grouped by e,
// dis = rsqrt(max(deg,1)); epilogue also produces sagg = dis[m,e]*T[m,ec]
// and stores dis for kernel 3's output scaling.
// ---------------------------------------------------------------------------
__global__ __launch_bounds__(256) void deg_kernel(const float* __restrict__ adj)
{
    int row = blockIdx.x;                    // b*N + n
    const float4* base = (const float4*)(adj + (size_t)row * 3072);
    int t = threadIdx.x;

    float s0 = 0.f, s1 = 0.f, s2 = 0.f;
#pragma unroll 3
    for (int it = 0; it < 3; it++) {
        int q = t + it * 256;                // float4 index, 768 total
        float4 v = base[q];
        int e0 = q % 3;                      // e of first component: (4q)%3 == q%3
        if (e0 == 0)      { s0 += v.x; s1 += v.y; s2 += v.z; s0 += v.w; }
        else if (e0 == 1) { s1 += v.x; s2 += v.y; s0 += v.z; s1 += v.w; }
        else              { s2 += v.x; s0 += v.y; s1 += v.z; s2 += v.w; }
    }

#pragma unroll
    for (int off = 16; off; off >>= 1) {
        s0 += __shfl_down_sync(0xffffffffu, s0, off);
        s1 += __shfl_down_sync(0xffffffffu, s1, off);
        s2 += __shfl_down_sync(0xffffffffu, s2, off);
    }

    __shared__ float red[8][3];
    __shared__ float dis_s[3];
    int w = t >> 5, lane = t & 31;
    if (lane == 0) { red[w][0] = s0; red[w][1] = s1; red[w][2] = s2; }
    __syncthreads();

    if (t < 3) {
        float tot = 0.f;
#pragma unroll
        for (int i = 0; i < 8; i++) tot += red[i][t];
        float d = rsqrtf(fmaxf(tot, 1.0f));
        dis_s[t] = d;
        g_dis[(size_t)row * 3 + t] = d;
    }
    __syncthreads();

    if (t < 96) g_sagg[(size_t)row * 96 + t] = dis_s[t >> 5] * g_T[(size_t)row * 96 + t];
}

// ---------------------------------------------------------------------------
// Kernel 3: fused aggregation GEMM.
//   out[b,n,c] = mask * ( sum_e dis[n,e] * sum_m adj[b,n,m,e]*sagg[b,m,e,c]
//                         + sum_e S[b,n,e*32+c] )
// Block = 256 threads, 32 n-rows (TN=32). Streams m in chunks of 32 (TM=32).
// adj deinterleaved to adj_s[e][n][m] (m-contiguous for LDS.128 broadcast);
// sagg transposed to sagg_s[e][c][m+pad36] (m-contiguous per lane, 4-phase
// conflict-free .128). Warp w owns rows 4w..4w+3, lane = c. One warp FFMA
// covers all 32 output channels of one adj element.
// ---------------------------------------------------------------------------
__global__ __launch_bounds__(256) void agg_kernel(
    const float* __restrict__ adj,
    const int* __restrict__ mask,
    float* __restrict__ out)
{
    __shared__ __align__(16) float adj_s[3][32][32];    // 12 KB
    __shared__ __align__(16) float sagg_s[3][32][36];   // 13.5 KB (pad for .128 banks)

    int t = threadIdx.x, w = t >> 5, lane = t & 31;
    int b = blockIdx.y;
    int n0 = blockIdx.x * 32;

    const float* adjb  = adj    + ((size_t)b * Nn + n0) * Nn * 3;
    const float* saggb = g_sagg + (size_t)b * Nn * 96;

    float acc[4][3];
#pragma unroll
    for (int i = 0; i < 4; i++)
#pragma unroll
        for (int e = 0; e < 3; e++) acc[i][e] = 0.f;

    for (int m0 = 0; m0 < Nn; m0 += 32) {
        __syncthreads();  // previous chunk's compute done before overwrite

        // Load + deinterleave adj chunk: 32 rows x 96 floats (m-local 0..31, e 0..2)
#pragma unroll 3
        for (int it = 0; it < 3; it++) {
            int q = t + it * 256;            // 768 float4s
            int i = q / 24, rr = q % 24;
            float4 v = *(const float4*)(adjb + (size_t)i * (Nn * 3) + m0 * 3 + rr * 4);
            int f = rr * 4;
            adj_s[(f    ) % 3][i][(f    ) / 3] = v.x;
            adj_s[(f + 1) % 3][i][(f + 1) / 3] = v.y;
            adj_s[(f + 2) % 3][i][(f + 2) / 3] = v.z;
            adj_s[(f + 3) % 3][i][(f + 3) / 3] = v.w;
        }
        // Load + transpose sagg chunk: rows m0..m0+31, 96 floats each -> [e][c][m]
#pragma unroll 3
        for (int it = 0; it < 3; it++) {
            int q = t + it * 256;
            int m = q / 24, rr = q % 24;
            float4 v = *(const float4*)(saggb + (size_t)(m0 + m) * 96 + rr * 4);
            int f = rr * 4;                  // ec of first comp; all 4 share e
            int e = f >> 5, c0 = f & 31;
            sagg_s[e][c0    ][m] = v.x;
            sagg_s[e][c0 + 1][m] = v.y;
            sagg_s[e][c0 + 2][m] = v.z;
            sagg_s[e][c0 + 3][m] = v.w;
        }
        __syncthreads();

        int i0 = w * 4;
#pragma unroll
        for (int mq = 0; mq < 8; mq++) {
            float4 sg0 = *(const float4*)&sagg_s[0][lane][4 * mq];
            float4 sg1 = *(const float4*)&sagg_s[1][lane][4 * mq];
            float4 sg2 = *(const float4*)&sagg_s[2][lane][4 * mq];
#pragma unroll
            for (int i = 0; i < 4; i++) {
                float4 a0 = *(const float4*)&adj_s[0][i0 + i][4 * mq];
                float4 a1 = *(const float4*)&adj_s[1][i0 + i][4 * mq];
                float4 a2 = *(const float4*)&adj_s[2][i0 + i][4 * mq];
                acc[i][0] += a0.x * sg0.x + a0.y * sg0.y + a0.z * sg0.z + a0.w * sg0.w;
                acc[i][1] += a1.x * sg1.x + a1.y * sg1.y + a1.z * sg1.z + a1.w * sg1.w;
                acc[i][2] += a2.x * sg2.x + a2.y * sg2.y + a2.z * sg2.z + a2.w * sg2.w;
            }
        }
    }

    // Epilogue: scale by dis[n,e], add self term, apply mask
#pragma unroll
    for (int i = 0; i < 4; i++) {
        int n = n0 + w * 4 + i;
        size_t rown = (size_t)b * Nn + n;
        float d0 = g_dis[rown * 3 + 0];
        float d1 = g_dis[rown * 3 + 1];
        float d2 = g_dis[rown * 3 + 2];
        const float* Sp = g_S + rown * 96;
        float sv = Sp[lane] + Sp[32 + lane] + Sp[64 + lane];
        float val = d0 * acc[i][0] + d1 * acc[i][1] + d2 * acc[i][2] + sv;
        if (mask[rown] == 0) val = 0.f;
        out[rown * 32 + lane] = val;
    }
}

// ---------------------------------------------------------------------------
extern "C" void kernel_launch(void* const* d_in, const int* in_sizes, int n_in,
                              void* d_out, int out_size)
{
    const float* x    = (const float*)d_in[0];         // [16,1024,32]
    const float* adj  = (const float*)d_in[1];         // [16,1024,1024,3]
    const int*   mask = (const int*)d_in[2];           // [16,1024] bool -> int32
    const float* W    = (const float*)d_in[3];         // [32,96]
    const float* W0   = (const float*)d_in[4];         // [32,96]
    const float* b0   = (const float*)d_in[5];         // [96]
    float*       out  = (float*)d_out;                 // [16,1024,32]

    (void)in_sizes; (void)n_in; (void)out_size;

    prep_kernel<<<512, 384>>>(x, W, W0, b0);
    deg_kernel<<<Bn * Nn, 256>>>(adj);
    agg_kernel<<<dim3(Nn / 32, Bn), 256>>>(adj, mask, out);
}

// round 5
// speedup vs baseline: 1.5813x; 1.5813x over previous
#include <cuda_runtime.h>
#include <cstdint>

#define Bn  16
#define Nn  1024

// Scratch (device globals; no allocation allowed)
__device__ __align__(16) float g_T[Bn * Nn * 96];       // x @ W            [row][ec]
__device__ __align__(16) float g_S[Bn * Nn * 96];       // x @ W0 + b0      [row][ec]
__device__ __align__(16) float g_saggT[Bn * 96 * Nn];   // dis[m,e]*T, transposed: [b][ec][m]
__device__ __align__(16) float g_dis[Bn * Nn * 3];      // deg^-1/2         [row][e]

__device__ __forceinline__ uint32_t sptr(const void* p) {
    return (uint32_t)__cvta_generic_to_shared(p);
}
#define LDSV2(lo, hi, a) \
    asm volatile("ld.shared.v2.b64 {%0,%1}, [%2];" : "=l"(lo), "=l"(hi) : "r"(a))
#define FFMA2(d, a, b) \
    asm volatile("fma.rn.f32x2 %0, %1, %2, %0;" : "+l"(d) : "l"(a), "l"(b))
#define CPASYNC16(dst, src) \
    asm volatile("cp.async.cg.shared.global [%0], [%1], 16;" :: "r"(dst), "l"(src))
#define UNPACK2(lo, hi, v) \
    asm volatile("mov.b64 {%0,%1}, %2;" : "=f"(lo), "=f"(hi) : "l"(v))

// ---------------------------------------------------------------------------
// Kernel 1: T = x@W, S = x@W0 + b0.  Block=384 (12 warps) covers 32 rows.
// Warp g handles output columns g*16..g*16+15 for all 32 rows (lane = row):
// weight reads are warp-broadcast (conflict-free), xs pad-33 conflict-free.
// ---------------------------------------------------------------------------
__global__ __launch_bounds__(384) void prep_kernel(
    const float* __restrict__ x,
    const float* __restrict__ W,
    const float* __restrict__ W0,
    const float* __restrict__ b0)
{
    __shared__ __align__(16) float Wc[32 * 192];
    __shared__ float b0s[96];
    __shared__ float xs[32][33];

    int t = threadIdx.x;
    for (int i = t; i < 32 * 192; i += 384) {
        int k = i / 192, j = i % 192;
        Wc[i] = (j < 96) ? W[k * 96 + j] : W0[k * 96 + (j - 96)];
    }
    if (t < 96) b0s[t] = b0[t];

    int row0 = blockIdx.x * 32;
    for (int i = t; i < 32 * 32; i += 384)
        xs[i >> 5][i & 31] = x[(size_t)(row0 + (i >> 5)) * 32 + (i & 31)];
    __syncthreads();

    int g = t >> 5, r = t & 31;     // warp-uniform g, lane = row
    int row = row0 + r;

    float acc[16];
#pragma unroll
    for (int j = 0; j < 16; j++) acc[j] = 0.f;

#pragma unroll 4
    for (int k = 0; k < 32; k++) {
        float xv = xs[r][k];
        const float4* wp = (const float4*)&Wc[k * 192 + g * 16];   // broadcast
        float4 w0v = wp[0], w1v = wp[1], w2v = wp[2], w3v = wp[3];
        acc[0]  += xv * w0v.x; acc[1]  += xv * w0v.y; acc[2]  += xv * w0v.z; acc[3]  += xv * w0v.w;
        acc[4]  += xv * w1v.x; acc[5]  += xv * w1v.y; acc[6]  += xv * w1v.z; acc[7]  += xv * w1v.w;
        acc[8]  += xv * w2v.x; acc[9]  += xv * w2v.y; acc[10] += xv * w2v.z; acc[11] += xv * w2v.w;
        acc[12] += xv * w3v.x; acc[13] += xv * w3v.y; acc[14] += xv * w3v.z; acc[15] += xv * w3v.w;
    }

    if (g < 6) {
        float4* dst = (float4*)&g_T[(size_t)row * 96 + g * 16];
#pragma unroll
        for (int q = 0; q < 4; q++)
            dst[q] = make_float4(acc[q*4], acc[q*4+1], acc[q*4+2], acc[q*4+3]);
    } else {
        int off = (g - 6) * 16;
        float4* dst = (float4*)&g_S[(size_t)row * 96 + off];
#pragma unroll
        for (int q = 0; q < 4; q++)
            dst[q] = make_float4(acc[q*4]   + b0s[off + q*4],
                                 acc[q*4+1] + b0s[off + q*4 + 1],
                                 acc[q*4+2] + b0s[off + q*4 + 2],
                                 acc[q*4+3] + b0s[off + q*4 + 3]);
    }
}

// ---------------------------------------------------------------------------
// Kernel 2: degrees.  One block per (b,n) row: dis = rsqrt(max(deg,1)).
// ---------------------------------------------------------------------------
__global__ __launch_bounds__(256) void deg_kernel(const float* __restrict__ adj)
{
    int row = blockIdx.x;                    // b*N + n
    const float4* base = (const float4*)(adj + (size_t)row * 3072);
    int t = threadIdx.x;

    float s0 = 0.f, s1 = 0.f, s2 = 0.f;
#pragma unroll 3
    for (int it = 0; it < 3; it++) {
        int q = t + it * 256;                // float4 index, 768 total
        float4 v = base[q];
        int e0 = q % 3;                      // (4q)%3 == q%3
        if (e0 == 0)      { s0 += v.x; s1 += v.y; s2 += v.z; s0 += v.w; }
        else if (e0 == 1) { s1 += v.x; s2 += v.y; s0 += v.z; s1 += v.w; }
        else              { s2 += v.x; s0 += v.y; s1 += v.z; s2 += v.w; }
    }
#pragma unroll
    for (int off = 16; off; off >>= 1) {
        s0 += __shfl_down_sync(0xffffffffu, s0, off);
        s1 += __shfl_down_sync(0xffffffffu, s1, off);
        s2 += __shfl_down_sync(0xffffffffu, s2, off);
    }
    __shared__ float red[8][3];
    int w = t >> 5, lane = t & 31;
    if (lane == 0) { red[w][0] = s0; red[w][1] = s1; red[w][2] = s2; }
    __syncthreads();
    if (t < 3) {
        float tot = 0.f;
#pragma unroll
        for (int i = 0; i < 8; i++) tot += red[i][t];
        g_dis[(size_t)row * 3 + t] = rsqrtf(fmaxf(tot, 1.0f));
    }
}

// ---------------------------------------------------------------------------
// Kernel 3: transpose + scale: g_saggT[b][ec][m] = dis[b,m,e] * T[b,m,ec].
// Block = (b, 64-row m tile), 256 threads. Coalesced in and out.
// ---------------------------------------------------------------------------
__global__ __launch_bounds__(256) void trans_kernel()
{
    __shared__ float Ts[64][97];
    __shared__ float ds[64][3];
    int b = blockIdx.y, m0 = blockIdx.x * 64;
    int t = threadIdx.x;
    const float* Tb = g_T + ((size_t)b * Nn + m0) * 96;

#pragma unroll 6
    for (int it = 0; it < 6; it++) {
        int q = t + it * 256;                // 1536 float4
        int m = q / 24, rr = q % 24;
        float4 v = *(const float4*)(Tb + (size_t)m * 96 + rr * 4);
        Ts[m][rr*4]   = v.x; Ts[m][rr*4+1] = v.y;
        Ts[m][rr*4+2] = v.z; Ts[m][rr*4+3] = v.w;
    }
    if (t < 192) ds[t / 3][t % 3] = g_dis[((size_t)b * Nn + m0 + t / 3) * 3 + (t % 3)];
    __syncthreads();

    float* Ob = g_saggT + (size_t)b * 96 * Nn;
#pragma unroll 6
    for (int it = 0; it < 6; it++) {
        int q = t + it * 256;
        int ec = q >> 4, mm = q & 15;
        int e = ec >> 5;
        float4 o;
        o.x = Ts[mm*4+0][ec] * ds[mm*4+0][e];
        o.y = Ts[mm*4+1][ec] * ds[mm*4+1][e];
        o.z = Ts[mm*4+2][ec] * ds[mm*4+2][e];
        o.w = Ts[mm*4+3][ec] * ds[mm*4+3][e];
        *(float4*)(Ob + (size_t)ec * Nn + m0 + mm * 4) = o;
    }
}

// ---------------------------------------------------------------------------
// Kernel 4: fused aggregation GEMM with FFMA2 (f32x2) accumulators.
//   out[b,n,c] = mask * ( sum_e dis[n,e] * sum_m adj[b,n,m,e]*saggT[b,ec,m]
//                         + sum_e S[b,n,e*32+c] )
// Block = 128 thr (4 warps), 32 n-rows; warp w owns rows 8w..8w+7, lane = c.
// m streamed in chunks of 32: sagg double-buffered via cp.async (layout
// [e][c][m], pad 36 -> 144B rows keep 16B alignment + conflict-free v2.b64);
// adj prefetched to regs during compute, deinterleaved to [e][i][m] so
// (m,m+1) pairs are register-adjacent for fma.rn.f32x2.
// ---------------------------------------------------------------------------
__global__ __launch_bounds__(128) void agg_kernel(
    const float* __restrict__ adj,
    const int* __restrict__ mask,
    float* __restrict__ out)
{
    __shared__ __align__(16) float adj_s[3][32][32];        // 12 KB
    __shared__ __align__(16) float sagg_s[2][3][32][36];    // 27 KB

    int t = threadIdx.x, w = t >> 5, lane = t & 31;
    int b = blockIdx.y, n0 = blockIdx.x * 32;
    const float* adjb = adj + ((size_t)b * Nn + n0) * (Nn * 3);
    const float* stb  = g_saggT + (size_t)b * 96 * Nn;

    uint32_t sagg_base = sptr(&sagg_s[0][0][0][0]);
    uint32_t adj_base  = sptr(&adj_s[0][0][0]);

    // loop-invariant per-thread load indices
    int ai[6], ar[6], sec[6], smm[6];
#pragma unroll
    for (int it = 0; it < 6; it++) {
        int q = t + it * 128;
        ai[it] = q / 24; ar[it] = q % 24;    // adj: row i, float4 rr
        sec[it] = q >> 3; smm[it] = q & 7;   // sagg: ec row, float4 mm
    }

    float4 av[6];
    auto ldg_adj = [&](int m0) {
#pragma unroll
        for (int it = 0; it < 6; it++)
            av[it] = *(const float4*)(adjb + (size_t)ai[it] * (Nn * 3) + m0 * 3 + ar[it] * 4);
    };
    auto sts_adj = [&]() {
#pragma unroll
        for (int it = 0; it < 6; it++) {
            int i = ai[it], f = ar[it] * 4;
            adj_s[(f    ) % 3][i][(f    ) / 3] = av[it].x;
            adj_s[(f + 1) % 3][i][(f + 1) / 3] = av[it].y;
            adj_s[(f + 2) % 3][i][(f + 2) / 3] = av[it].z;
            adj_s[(f + 3) % 3][i][(f + 3) / 3] = av[it].w;
        }
    };
    auto cp_sagg = [&](int s, int m0) {
#pragma unroll
        for (int it = 0; it < 6; it++) {
            uint32_t dst = sagg_base + (uint32_t)s * 13824u + sec[it] * 144u + smm[it] * 16u;
            CPASYNC16(dst, stb + (size_t)sec[it] * Nn + m0 + smm[it] * 4);
        }
        asm volatile("cp.async.commit_group;" ::: "memory");
    };

    // prologue: chunk 0
    ldg_adj(0);
    cp_sagg(0, 0);
    asm volatile("cp.async.wait_group 0;" ::: "memory");
    sts_adj();
    __syncthreads();

    uint64_t acc2[8][3];
#pragma unroll
    for (int i = 0; i < 8; i++)
#pragma unroll
        for (int e = 0; e < 3; e++) acc2[i][e] = 0ull;  // (0.f,0.f)

    int i0 = w * 8;
    for (int k = 0; k < 32; k++) {
        int cb = k & 1;
        if (k < 31) {                        // prefetch next chunk
            ldg_adj((k + 1) * 32);
            cp_sagg(cb ^ 1, (k + 1) * 32);
        }

        uint32_t sgb = sagg_base + (uint32_t)cb * 13824u + (uint32_t)lane * 144u;
#pragma unroll
        for (int mq = 0; mq < 8; mq++) {
            uint64_t s0[3], s1[3];
#pragma unroll
            for (int e = 0; e < 3; e++)
                LDSV2(s0[e], s1[e], sgb + (uint32_t)e * 4608u + (uint32_t)mq * 16u);
#pragma unroll
            for (int i = 0; i < 8; i++) {
#pragma unroll
                for (int e = 0; e < 3; e++) {
                    uint64_t a0, a1;
                    LDSV2(a0, a1, adj_base + (uint32_t)e * 4096u
                                  + (uint32_t)(i0 + i) * 128u + (uint32_t)mq * 16u);
                    FFMA2(acc2[i][e], a0, s0[e]);
                    FFMA2(acc2[i][e], a1, s1[e]);
                }
            }
        }
        __syncthreads();                     // all warps done reading adj_s
        if (k < 31) {
            sts_adj();                       // fill adj_s with chunk k+1
            asm volatile("cp.async.wait_group 0;" ::: "memory");
        }
        __syncthreads();                     // stores + cp.async visible
    }

    // epilogue: combine pair-sums, scale by dis[n,e], add self term, mask
#pragma unroll
    for (int i = 0; i < 8; i++) {
        int n = n0 + i0 + i;
        size_t rown = (size_t)b * Nn + n;
        float d0 = g_dis[rown * 3 + 0];
        float d1 = g_dis[rown * 3 + 1];
        float d2 = g_dis[rown * 3 + 2];
        float lo, hi, a0, a1, a2;
        UNPACK2(lo, hi, acc2[i][0]); a0 = lo + hi;
        UNPACK2(lo, hi, acc2[i][1]); a1 = lo + hi;
        UNPACK2(lo, hi, acc2[i][2]); a2 = lo + hi;
        const float* Sp = g_S + rown * 96;
        float sv = Sp[lane] + Sp[32 + lane] + Sp[64 + lane];
        float val = d0 * a0 + d1 * a1 + d2 * a2 + sv;
        if (mask[rown] == 0) val = 0.f;
        out[rown * 32 + lane] = val;
    }
}

// ---------------------------------------------------------------------------
extern "C" void kernel_launch(void* const* d_in, const int* in_sizes, int n_in,
                              void* d_out, int out_size)
{
    const float* x    = (const float*)d_in[0];   // [16,1024,32]
    const float* adj  = (const float*)d_in[1];   // [16,1024,1024,3]
    const int*   mask = (const int*)d_in[2];     // [16,1024] bool -> int32
    const float* W    = (const float*)d_in[3];   // [32,96]
    const float* W0   = (const float*)d_in[4];   // [32,96]
    const float* b0   = (const float*)d_in[5];   // [96]
    float*       out  = (float*)d_out;           // [16,1024,32]

    (void)in_sizes; (void)n_in; (void)out_size;

    prep_kernel<<<512, 384>>>(x, W, W0, b0);
    deg_kernel<<<Bn * Nn, 256>>>(adj);
    trans_kernel<<<dim3(Nn / 64, Bn), 256>>>();
    agg_kernel<<<dim3(Nn / 32, Bn), 128>>>(adj, mask, out);
}